// round 4
// baseline (speedup 1.0000x reference)
#include <cuda_runtime.h>
#include <cstdint>

// Problem constants (B=8, S=4096, D=512, H=1024, E=8, K=2)
#define NUM_TOK 32768
#define DDIM 512
#define HDIM 1024
#define NEXP 8

#define SSTR 136   // smem row stride (floats); 136 % 32 == 8 -> conflict-free patterns

// -------- device scratch --------
__device__ int   g_cnt[NEXP];
__device__ int   g_list[NEXP][NUM_TOK];
__device__ float g_gatev[NUM_TOK * 2];
__device__ float g_hbuf[(size_t)NUM_TOK * 2 * HDIM];

// -------- helpers --------
__device__ __forceinline__ float tf32r(float x) {
    uint32_t u;
    asm("cvt.rna.tf32.f32 %0, %1;" : "=r"(u) : "f"(x));
    return __uint_as_float(u);
}

__device__ __forceinline__ void mma_tf32(float* c, const uint32_t* a, const uint32_t* b) {
    asm volatile(
        "mma.sync.aligned.m16n8k8.row.col.f32.tf32.tf32.f32 "
        "{%0,%1,%2,%3}, {%4,%5,%6,%7}, {%8,%9}, {%0,%1,%2,%3};\n"
        : "+f"(c[0]), "+f"(c[1]), "+f"(c[2]), "+f"(c[3])
        : "r"(a[0]), "r"(a[1]), "r"(a[2]), "r"(a[3]),
          "r"(b[0]), "r"(b[1]));
}

// -------- zero out + counters --------
__global__ void zero_kernel(float* __restrict__ out, long long n) {
    long long i = (long long)blockIdx.x * blockDim.x + threadIdx.x;
    long long stride = (long long)gridDim.x * blockDim.x;
    for (; i < n; i += stride) out[i] = 0.0f;
    if (blockIdx.x == 0 && threadIdx.x < NEXP) g_cnt[threadIdx.x] = 0;
}

// -------- router: one warp per token --------
__global__ void router_kernel(const float* __restrict__ x,
                              const float* __restrict__ rw,
                              const float* __restrict__ rb) {
    int gw   = (blockIdx.x * blockDim.x + threadIdx.x) >> 5;
    int lane = threadIdx.x & 31;
    if (gw >= NUM_TOK) return;
    const float* xr = x + (size_t)gw * DDIM;

    float acc[NEXP];
#pragma unroll
    for (int e = 0; e < NEXP; e++) acc[e] = 0.0f;
    for (int d = lane; d < DDIM; d += 32) {
        float xv = xr[d];
        const float* r = rw + (size_t)d * NEXP;
#pragma unroll
        for (int e = 0; e < NEXP; e++) acc[e] = fmaf(xv, r[e], acc[e]);
    }
#pragma unroll
    for (int off = 16; off > 0; off >>= 1) {
#pragma unroll
        for (int e = 0; e < NEXP; e++)
            acc[e] += __shfl_down_sync(0xffffffffu, acc[e], off);
    }
    if (lane == 0) {
#pragma unroll
        for (int e = 0; e < NEXP; e++) acc[e] += rb[e];
        int i0 = 0; float v0 = acc[0];
#pragma unroll
        for (int e = 1; e < NEXP; e++) if (acc[e] > v0) { v0 = acc[e]; i0 = e; }
        int i1 = -1; float v1 = -3.0e38f;
#pragma unroll
        for (int e = 0; e < NEXP; e++) if (e != i0 && acc[e] > v1) { v1 = acc[e]; i1 = e; }
        float e1  = expf(v1 - v0);
        float inv = 1.0f / (1.0f + e1);
        int p0 = atomicAdd(&g_cnt[i0], 1);
        g_list[i0][p0] = gw * 2;
        g_gatev[gw * 2] = inv;
        int p1 = atomicAdd(&g_cnt[i1], 1);
        g_list[i1][p1] = gw * 2 + 1;
        g_gatev[gw * 2 + 1] = e1 * inv;
    }
}

// ============================================================
// Grouped TF32 GEMM: D(128x128) = A(128xK) @ B(KxNT slice)
//   G1:  A = x (gather tok),   B = w1[e] ([D][H], ld=HDIM), epi: bias+relu -> g_hbuf
//  !G1:  A = g_hbuf (slot),    B = w2[e] ([H][D], ld=DDIM), epi: gate*(v+bias) atomic-> out
// 128 threads, 4 warps (2x2), warp tile 64x64, BK=16 double-buffered.
// ============================================================
template<int KT, bool G1>
__global__ __launch_bounds__(128, 2)
void gemm_kernel(const float* __restrict__ x,
                 const float* __restrict__ W,
                 const float* __restrict__ bias,
                 float* __restrict__ out) {
    const int K  = KT * 16;
    const int NT = G1 ? HDIM : DDIM;

    int e   = blockIdx.y;
    int cnt = g_cnt[e];
    int m0  = blockIdx.x * 128;
    if (m0 >= cnt) return;
    int rows = min(cnt - m0, 128);
    int n0 = blockIdx.z * 128;

    __shared__ float As[2][16][SSTR];   // [k][m] transposed
    __shared__ float Bs[2][16][SSTR];   // [k][n]
    __shared__ int   s_slot[128];
    __shared__ float s_gate[128];

    int tid = threadIdx.x;   // 0..127

    {
        int r = tid < rows ? tid : rows - 1;
        int slot = g_list[e][m0 + r];
        s_slot[tid] = slot;
        if (!G1) s_gate[tid] = g_gatev[slot];
    }
    __syncthreads();

    const float* A  = G1 ? x : g_hbuf;
    const float* Bg = W + (size_t)e * DDIM * HDIM + n0;   // B[k][n] at Bg[k*NT + n]

    // loader assignment (128 threads)
    int arow = tid;                         // A row in tile
    int aslotrow = G1 ? (s_slot[arow] >> 1) : s_slot[arow];
    const float* aRow = A + (size_t)aslotrow * K;
    int blk = tid >> 3;                     // B k-row 0..15
    int blc = (tid & 7) * 16;               // B col start (floats)

    // warp / lane mapping (2x2 warp grid, warp tile 64x64)
    int wid = tid >> 5, lane = tid & 31;
    int g = lane >> 2, t = lane & 3;
    int wm = (wid >> 1) * 64;
    int wn = (wid & 1) * 64;

    float acc[4][8][4] = {};

    float4 av[4], bv[4];
#pragma unroll
    for (int v = 0; v < 4; v++) {
        av[v] = *(const float4*)(aRow + 4 * v);
        bv[v] = *(const float4*)(Bg + (size_t)blk * NT + blc + 4 * v);
    }

    auto stsA = [&](int b) {
#pragma unroll
        for (int v = 0; v < 4; v++) {
            As[b][4 * v + 0][arow] = tf32r(av[v].x);
            As[b][4 * v + 1][arow] = tf32r(av[v].y);
            As[b][4 * v + 2][arow] = tf32r(av[v].z);
            As[b][4 * v + 3][arow] = tf32r(av[v].w);
        }
    };
    auto stsB = [&](int b) {
#pragma unroll
        for (int v = 0; v < 4; v++) {
            float4 c = make_float4(tf32r(bv[v].x), tf32r(bv[v].y),
                                   tf32r(bv[v].z), tf32r(bv[v].w));
            *(float4*)&Bs[b][blk][blc + 4 * v] = c;
        }
    };

    stsA(0);
    stsB(0);
    __syncthreads();

    int buf = 0;
    for (int kb = 0; kb < KT; kb++) {
        if (kb + 1 < KT) {
            int k0 = (kb + 1) * 16;
#pragma unroll
            for (int v = 0; v < 4; v++) {
                av[v] = *(const float4*)(aRow + k0 + 4 * v);
                bv[v] = *(const float4*)(Bg + (size_t)(k0 + blk) * NT + blc + 4 * v);
            }
        }
#pragma unroll
        for (int ks = 0; ks < 16; ks += 8) {
            uint32_t a[4][4], bf[8][2];
#pragma unroll
            for (int i = 0; i < 4; i++) {
                int m = wm + 16 * i;
                a[i][0] = __float_as_uint(As[buf][ks + t][m + g]);
                a[i][1] = __float_as_uint(As[buf][ks + t][m + g + 8]);
                a[i][2] = __float_as_uint(As[buf][ks + t + 4][m + g]);
                a[i][3] = __float_as_uint(As[buf][ks + t + 4][m + g + 8]);
            }
#pragma unroll
            for (int j = 0; j < 8; j++) {
                int n = wn + 8 * j + g;
                bf[j][0] = __float_as_uint(Bs[buf][ks + t][n]);
                bf[j][1] = __float_as_uint(Bs[buf][ks + t + 4][n]);
            }
#pragma unroll
            for (int i = 0; i < 4; i++)
#pragma unroll
                for (int j = 0; j < 8; j++)
                    mma_tf32(acc[i][j], a[i], bf[j]);
        }
        if (kb + 1 < KT) {
            stsA(buf ^ 1);
            stsB(buf ^ 1);
        }
        __syncthreads();
        buf ^= 1;
    }

    // epilogue
    const float* be = bias + (size_t)e * NT + n0;
#pragma unroll
    for (int i = 0; i < 4; i++) {
#pragma unroll
        for (int rr = 0; rr < 2; rr++) {
            int r = wm + 16 * i + g + rr * 8;
            if (r < rows) {
                if (G1) {
                    float* hrow = g_hbuf + (size_t)s_slot[r] * HDIM + n0;
#pragma unroll
                    for (int j = 0; j < 8; j++) {
                        int c = wn + 8 * j + 2 * t;
                        float v0 = acc[i][j][rr * 2 + 0] + be[c];
                        float v1 = acc[i][j][rr * 2 + 1] + be[c + 1];
                        float2 o = make_float2(fmaxf(v0, 0.0f), fmaxf(v1, 0.0f));
                        *(float2*)&hrow[c] = o;
                    }
                } else {
                    int   tok = s_slot[r] >> 1;
                    float gt  = s_gate[r];
                    float* orow = out + (size_t)tok * DDIM + n0;
#pragma unroll
                    for (int j = 0; j < 8; j++) {
                        int c = wn + 8 * j + 2 * t;
                        atomicAdd(&orow[c],     gt * (acc[i][j][rr * 2 + 0] + be[c]));
                        atomicAdd(&orow[c + 1], gt * (acc[i][j][rr * 2 + 1] + be[c + 1]));
                    }
                }
            }
        }
    }
}

// -------- expert usage tail --------
__global__ void usage_kernel(float* __restrict__ out, long long out_size) {
    int e = threadIdx.x;
    if (e < NEXP && out_size >= (long long)NUM_TOK * DDIM + NEXP)
        out[(long long)NUM_TOK * DDIM + e] = (float)g_cnt[e];
}

extern "C" void kernel_launch(void* const* d_in, const int* in_sizes, int n_in,
                              void* d_out, int out_size) {
    const float* x  = (const float*)d_in[0];
    const float* rw = (const float*)d_in[1];
    const float* rb = (const float*)d_in[2];
    const float* w1 = (const float*)d_in[3];
    const float* b1 = (const float*)d_in[4];
    const float* w2 = (const float*)d_in[5];
    const float* b2 = (const float*)d_in[6];
    float* out = (float*)d_out;

    zero_kernel<<<2048, 256>>>(out, (long long)NUM_TOK * DDIM);
    router_kernel<<<(NUM_TOK * 32 + 255) / 256, 256>>>(x, rw, rb);

    // GEMM1: K = DDIM = 512 -> KT = 32,  N = HDIM -> grid.z = 8
    gemm_kernel<32, true><<<dim3(256, NEXP, HDIM / 128), 128>>>(x, w1, b1, nullptr);
    // GEMM2: K = HDIM = 1024 -> KT = 64, N = DDIM -> grid.z = 4
    gemm_kernel<64, false><<<dim3(256, NEXP, DDIM / 128), 128>>>(x, w2, b2, out);

    usage_kernel<<<1, 32>>>(out, (long long)out_size);
}